// round 15
// baseline (speedup 1.0000x reference)
// Transformer encoder block — Round 10: flash QB=64 / 128-thr / 2 CTAs-per-SM;
// dense tcgemm unchanged from R9 (3-stage, BN=128, ldmatrix).
// B=16, S=577, EMB=768, HEADS=12, DK=64, DFF=3072.

#include <cuda_runtime.h>
#include <cstdint>
#include <math.h>

#define EMB   768
#define HEADS 12
#define DK    64
#define DFF   3072
#define BATCH 16
#define SEQ   577
#define SEQP  600
#define NTOK  (BATCH * SEQ)           // 9232
#define NBH   (BATCH * HEADS)         // 192
#define QKVW  (3 * EMB)               // 2304
#define QB    64                      // flash Q rows per block (4 warps)
#define KB    64
#define NKB   ((SEQ + KB - 1) / KB)   // 10

// ---------------- scratch (device globals) -----------------------------------
__device__ float g_h   [NTOK * EMB];
__device__ float g_qkv [(size_t)NTOK * QKVW];
__device__ float g_vT  [(size_t)NBH * DK * SEQP];
__device__ float g_ctx [NTOK * EMB];
__device__ float g_x2  [NTOK * EMB];
__device__ float g_h2  [NTOK * EMB];
__device__ float g_ff1 [(size_t)NTOK * DFF];
__device__ float g_wqkvT[QKVW * EMB];
__device__ float g_woT [EMB * EMB];
__device__ float g_w1T [DFF * EMB];
__device__ float g_w2T [EMB * DFF];
__device__ float g_bqkv[QKVW];

// ---------------- PTX helpers -------------------------------------------------
__device__ __forceinline__ uint32_t smem_u32(const void* p) {
    uint32_t a;
    asm("{ .reg .u64 t; cvta.to.shared.u64 t, %1; cvt.u32.u64 %0, t; }"
        : "=r"(a) : "l"(p));
    return a;
}
__device__ __forceinline__ float rnd_tf32(float x) {
    float r;
    asm("cvt.rna.tf32.f32 %0, %1;" : "=f"(r) : "f"(x));
    return r;
}
__device__ __forceinline__ void cp_async16(uint32_t dst, const void* src, int srcBytes) {
    asm volatile("cp.async.cg.shared.global [%0], [%1], 16, %2;"
                 :: "r"(dst), "l"(src), "r"(srcBytes) : "memory");
}
__device__ __forceinline__ void cp_commit() {
    asm volatile("cp.async.commit_group;" ::: "memory");
}
template <int N> __device__ __forceinline__ void cp_wait() {
    asm volatile("cp.async.wait_group %0;" :: "n"(N) : "memory");
}
__device__ __forceinline__ void mma_tf32(float* d, const uint32_t* a, const uint32_t* b) {
    asm volatile(
        "mma.sync.aligned.m16n8k8.row.col.f32.tf32.tf32.f32 "
        "{%0,%1,%2,%3}, {%4,%5,%6,%7}, {%8,%9}, {%0,%1,%2,%3};"
        : "+f"(d[0]), "+f"(d[1]), "+f"(d[2]), "+f"(d[3])
        : "r"(a[0]), "r"(a[1]), "r"(a[2]), "r"(a[3]), "r"(b[0]), "r"(b[1]));
}
// ldmatrix on 32-bit data: each 16B "row" = 4 tf32, distributed 4B/lane.
__device__ __forceinline__ void ldsm_x4(uint32_t* r, uint32_t addr) {
    asm volatile("ldmatrix.sync.aligned.m8n8.x4.shared.b16 {%0,%1,%2,%3}, [%4];"
        : "=r"(r[0]), "=r"(r[1]), "=r"(r[2]), "=r"(r[3]) : "r"(addr));
}
__device__ __forceinline__ void ldsm_x2(uint32_t* r, uint32_t addr) {
    asm volatile("ldmatrix.sync.aligned.m8n8.x2.shared.b16 {%0,%1}, [%2];"
        : "=r"(r[0]), "=r"(r[1]) : "r"(addr));
}

// ---------------- generic tf32 mma.sync GEMM (dense projections) --------------
// BM=128, BN=128, BK=32. 3-stage cp.async pipeline, single __syncthreads per
// chunk, 2 blocks/SM. (unchanged from R9)
template <int BN, bool BIAS, bool GELU, bool RES, bool RND>
__global__ void __launch_bounds__(256, 2) tcgemm(
    const float* __restrict__ A, const float* __restrict__ B,
    const float* __restrict__ bias, const float* __restrict__ res,
    float* __restrict__ C, int M, int N, int K,
    int lda, int ldb, int ldc)
{
    constexpr int WCOLS = 4;
    constexpr int WM = 64;
    constexpr int WN = BN / WCOLS;         // 32
    constexpr int MT = 4;
    constexpr int NT = WN / 8;             // 4
    constexpr int SA = 36;
    constexpr int ASTGF = 128 * SA;
    constexpr int BSTGF = BN * SA;
    constexpr int STGF  = ASTGF + BSTGF;

    extern __shared__ float smem[];
    const uint32_t sb = smem_u32(smem);
    const int tid = threadIdx.x;
    const int wid = tid >> 5, lane = tid & 31;
    const int g = lane >> 2, tig = lane & 3;
    const int wr = wid / WCOLS, wc = wid % WCOLS;
    const int wm0 = wr * WM, wn0 = wc * WN;

    const int aOff = (lane & 15) * SA + 4 * (lane >> 4);
    const int bOff = (lane & 7) * SA + 4 * ((lane >> 3) & 1);

    const int m0 = blockIdx.y * 128, n0 = blockIdx.x * BN;
    const int nCh = (K + 31) >> 5;

    auto loadA = [&](int c, int buf) {
        uint32_t base = sb + (uint32_t)(buf * STGF) * 4u;
        int k0 = c << 5;
        #pragma unroll
        for (int i = 0; i < 4; i++) {
            int s = tid + i * 256, r = s >> 3, sg = s & 7;
            int gm = m0 + r, kb = k0 + sg * 4;
            int bytes = 0;
            if (gm < M) { int rem = (K - kb) * 4; bytes = rem >= 16 ? 16 : (rem > 0 ? rem : 0); }
            const float* src = A + (size_t)(gm < M ? gm : 0) * lda + (kb < K ? kb : 0);
            cp_async16(base + (uint32_t)(r * SA * 4 + sg * 16), src, bytes);
        }
    };
    auto loadB = [&](int c, int buf) {
        uint32_t base = sb + (uint32_t)(buf * STGF + ASTGF) * 4u;
        int k0 = c << 5;
        #pragma unroll
        for (int i = 0; i < BN / 32; i++) {
            int s = tid + i * 256, r = s >> 3, sg = s & 7;
            int gn = n0 + r, kb = k0 + sg * 4;
            int bytes = 0;
            if (gn < N) { int rem = (K - kb) * 4; bytes = rem >= 16 ? 16 : (rem > 0 ? rem : 0); }
            const float* src = B + (size_t)(gn < N ? gn : 0) * ldb + (kb < K ? kb : 0);
            cp_async16(base + (uint32_t)(r * SA * 4 + sg * 16), src, bytes);
        }
    };

    float acc[MT][NT][4];
    #pragma unroll
    for (int i = 0; i < MT; i++)
        #pragma unroll
        for (int j = 0; j < NT; j++)
            #pragma unroll
            for (int q = 0; q < 4; q++) acc[i][j][q] = 0.f;

    loadA(0, 0); loadB(0, 0); cp_commit();
    if (1 < nCh) { loadA(1, 1); loadB(1, 1); } cp_commit();

    for (int c = 0; c < nCh; c++) {
        const int buf = c % 3;
        cp_wait<1>();
        __syncthreads();
        int p = c + 2;
        if (p < nCh) { loadA(p, p % 3); loadB(p, p % 3); }
        cp_commit();

        const uint32_t AsfB = sb + (uint32_t)(buf * STGF) * 4u;
        const uint32_t BsfB = AsfB + (uint32_t)ASTGF * 4u;
        #pragma unroll
        for (int ks = 0; ks < 4; ks++) {
            const int k = ks * 8;
            uint32_t af[MT][4], bf[NT][2];
            #pragma unroll
            for (int mt = 0; mt < MT; mt++)
                ldsm_x4(af[mt], AsfB + (uint32_t)((wm0 + mt * 16) * SA + aOff + k) * 4u);
            #pragma unroll
            for (int nt = 0; nt < NT; nt++)
                ldsm_x2(bf[nt], BsfB + (uint32_t)((wn0 + nt * 8) * SA + bOff + k) * 4u);
            #pragma unroll
            for (int mt = 0; mt < MT; mt++)
                #pragma unroll
                for (int nt = 0; nt < NT; nt++)
                    mma_tf32(acc[mt][nt], af[mt], bf[nt]);
        }
    }

    #pragma unroll
    for (int mt = 0; mt < MT; mt++) {
        #pragma unroll
        for (int nt = 0; nt < NT; nt++) {
            int gm = m0 + wm0 + mt * 16 + g;
            int gn = n0 + wn0 + nt * 8 + 2 * tig;
            #pragma unroll
            for (int half = 0; half < 2; half++) {
                int gmr = gm + half * 8;
                if (gmr >= M) continue;
                float v0 = acc[mt][nt][half * 2 + 0];
                float v1 = acc[mt][nt][half * 2 + 1];
                if (BIAS) { v0 += bias[gn]; v1 += bias[gn + 1]; }
                if (GELU) {
                    v0 = 0.5f * v0 * (1.0f + erff(v0 * 0.7071067811865475f));
                    v1 = 0.5f * v1 * (1.0f + erff(v1 * 0.7071067811865475f));
                }
                float* crow = C + (size_t)gmr * ldc;
                if (RES) {
                    const float* rrow = res + (size_t)gmr * ldc;
                    v0 += rrow[gn]; v1 += rrow[gn + 1];
                }
                if (RND) { v0 = rnd_tf32(v0); v1 = rnd_tf32(v1); }
                *reinterpret_cast<float2*>(crow + gn) = make_float2(v0, v1);
            }
        }
    }
}

// ---------------- fused flash attention: QB=64, 128 threads, 2 CTAs/SM --------
// grid (10, NBH); 4 warps; warp w owns Q rows 16w..16w+15 of the 64-row block.
// smem: Qs[64][68] (reused as Ps), Ks[2][64][68], Vs[2][64][68] = 87 KB.
__global__ void __launch_bounds__(128, 2) flash_kernel(
    const float* __restrict__ qkv, const float* __restrict__ vT,
    float* __restrict__ ctx)
{
    constexpr int ST = 68;
    extern __shared__ float fsm[];
    float* Qs = fsm;
    const uint32_t sb = smem_u32(fsm);
    const uint32_t ks_off = QB * ST * 4u;                 // Q region: 64 rows
    const uint32_t vs_off = ks_off + 2 * 64 * ST * 4u;

    const int tid = threadIdx.x, wid = tid >> 5, lane = tid & 31;
    const int g = lane >> 2, tig = lane & 3;
    const int wm0 = wid * 16;                              // 0..48
    const int z = blockIdx.y, b = z / HEADS, h = z % HEADS;
    const int m0 = blockIdx.x * QB;

    const int aOff = (lane & 15) * ST + 4 * (lane >> 4);
    const int bOff = (lane & 7) * ST + 4 * ((lane >> 3) & 1);

    const float* Qg = qkv + (size_t)b * SEQ * QKVW + h * DK;
    const float* Kg = qkv + (size_t)b * SEQ * QKVW + EMB + h * DK;
    const float* Vg = vT + (size_t)z * DK * SEQP;

    // Q tile: 64 rows x 16 chunks = 1024 chunks over 128 threads (8 iters)
    #pragma unroll
    for (int i = 0; i < 8; i++) {
        int s = tid + i * 128, r = s >> 4, sg = s & 15;
        int gm = m0 + r;
        int bytes = (gm < SEQ) ? 16 : 0;
        cp_async16(sb + (uint32_t)(r * ST + sg * 4) * 4u,
                   Qg + (size_t)(gm < SEQ ? gm : 0) * QKVW + sg * 4, bytes);
    }
    cp_commit();

    auto loadKV = [&](int j, int buf) {
        int k0 = j * KB;
        #pragma unroll
        for (int i = 0; i < 8; i++) {      // K: 64x16 = 1024 chunks
            int s = tid + i * 128, r = s >> 4, sg = s & 15;
            int gs = k0 + r;
            int bytes = (gs < SEQ) ? 16 : 0;
            cp_async16(sb + ks_off + (uint32_t)(buf * 64 * ST + r * ST + sg * 4) * 4u,
                       Kg + (size_t)(gs < SEQ ? gs : 0) * QKVW + sg * 4, bytes);
        }
        #pragma unroll
        for (int i = 0; i < 8; i++) {      // V: 64x16 = 1024 chunks
            int s = tid + i * 128, r = s >> 4, sg = s & 15;
            int col = k0 + sg * 4;
            int bytes = (col + 4 <= SEQP) ? 16 : 0;
            cp_async16(sb + vs_off + (uint32_t)(buf * 64 * ST + r * ST + sg * 4) * 4u,
                       Vg + (size_t)r * SEQP + (bytes ? col : 0), bytes);
        }
    };
    loadKV(0, 0);
    cp_commit();

    cp_wait<1>();
    __syncthreads();
    uint32_t qf[8][4];
    #pragma unroll
    for (int ks = 0; ks < 8; ks++)
        ldsm_x4(qf[ks], sb + (uint32_t)(wm0 * ST + aOff + ks * 8) * 4u);

    float m_r0 = -1e30f, m_r1 = -1e30f, l_r0 = 0.f, l_r1 = 0.f;
    float acc_o[8][4];
    #pragma unroll
    for (int nt = 0; nt < 8; nt++)
        #pragma unroll
        for (int q = 0; q < 4; q++) acc_o[nt][q] = 0.f;

    for (int j = 0; j < NKB; j++) {
        const int buf = j & 1;
        cp_wait<0>();
        __syncthreads();
        if (j + 1 < NKB) loadKV(j + 1, buf ^ 1);
        cp_commit();

        const uint32_t KbB = sb + ks_off + (uint32_t)(buf * 64 * ST) * 4u;
        const uint32_t VbB = sb + vs_off + (uint32_t)(buf * 64 * ST) * 4u;

        float s_acc[8][4];
        #pragma unroll
        for (int nt = 0; nt < 8; nt++)
            #pragma unroll
            for (int q = 0; q < 4; q++) s_acc[nt][q] = 0.f;
        #pragma unroll
        for (int ks = 0; ks < 8; ks++) {
            const int k = ks * 8;
            uint32_t bf[8][2];
            #pragma unroll
            for (int nt = 0; nt < 8; nt++)
                ldsm_x2(bf[nt], KbB + (uint32_t)(nt * 8 * ST + bOff + k) * 4u);
            #pragma unroll
            for (int nt = 0; nt < 8; nt++)
                mma_tf32(s_acc[nt], qf[ks], bf[nt]);
        }

        const int colbase = j * KB;
        float mx0 = -1e30f, mx1 = -1e30f;
        #pragma unroll
        for (int nt = 0; nt < 8; nt++) {
            int c0 = colbase + nt * 8 + 2 * tig;
            if (c0 >= SEQ)     { s_acc[nt][0] = -1e30f; s_acc[nt][2] = -1e30f; }
            if (c0 + 1 >= SEQ) { s_acc[nt][1] = -1e30f; s_acc[nt][3] = -1e30f; }
            mx0 = fmaxf(mx0, fmaxf(s_acc[nt][0], s_acc[nt][1]));
            mx1 = fmaxf(mx1, fmaxf(s_acc[nt][2], s_acc[nt][3]));
        }
        mx0 = fmaxf(mx0, __shfl_xor_sync(0xffffffffu, mx0, 1));
        mx0 = fmaxf(mx0, __shfl_xor_sync(0xffffffffu, mx0, 2));
        mx1 = fmaxf(mx1, __shfl_xor_sync(0xffffffffu, mx1, 1));
        mx1 = fmaxf(mx1, __shfl_xor_sync(0xffffffffu, mx1, 2));

        float mn0 = fmaxf(m_r0, mx0), mn1 = fmaxf(m_r1, mx1);
        float al0 = __expf(m_r0 - mn0), al1 = __expf(m_r1 - mn1);
        m_r0 = mn0; m_r1 = mn1;

        float sum0 = 0.f, sum1 = 0.f;
        #pragma unroll
        for (int nt = 0; nt < 8; nt++) {
            s_acc[nt][0] = __expf(s_acc[nt][0] - mn0);
            s_acc[nt][1] = __expf(s_acc[nt][1] - mn0);
            s_acc[nt][2] = __expf(s_acc[nt][2] - mn1);
            s_acc[nt][3] = __expf(s_acc[nt][3] - mn1);
            sum0 += s_acc[nt][0] + s_acc[nt][1];
            sum1 += s_acc[nt][2] + s_acc[nt][3];
        }
        sum0 += __shfl_xor_sync(0xffffffffu, sum0, 1);
        sum0 += __shfl_xor_sync(0xffffffffu, sum0, 2);
        sum1 += __shfl_xor_sync(0xffffffffu, sum1, 1);
        sum1 += __shfl_xor_sync(0xffffffffu, sum1, 2);
        l_r0 = l_r0 * al0 + sum0;
        l_r1 = l_r1 * al1 + sum1;

        #pragma unroll
        for (int nt = 0; nt < 8; nt++) {
            acc_o[nt][0] *= al0; acc_o[nt][1] *= al0;
            acc_o[nt][2] *= al1; acc_o[nt][3] *= al1;
        }

        // P -> smem (own rows only), then O += P @ V
        #pragma unroll
        for (int nt = 0; nt < 8; nt++) {
            int col = nt * 8 + 2 * tig;
            *reinterpret_cast<float2*>(Qs + (wm0 + g) * ST + col) =
                make_float2(rnd_tf32(s_acc[nt][0]), rnd_tf32(s_acc[nt][1]));
            *reinterpret_cast<float2*>(Qs + (wm0 + g + 8) * ST + col) =
                make_float2(rnd_tf32(s_acc[nt][2]), rnd_tf32(s_acc[nt][3]));
        }
        __syncwarp();

        #pragma unroll
        for (int ks = 0; ks < 8; ks++) {
            const int k = ks * 8;
            uint32_t af[4], bf[8][2];
            ldsm_x4(af, sb + (uint32_t)(wm0 * ST + aOff + k) * 4u);
            #pragma unroll
            for (int nt = 0; nt < 8; nt++)
                ldsm_x2(bf[nt], VbB + (uint32_t)(nt * 8 * ST + bOff + k) * 4u);
            #pragma unroll
            for (int nt = 0; nt < 8; nt++)
                mma_tf32(acc_o[nt], af, bf[nt]);
        }
        __syncwarp();
    }

    float inv0 = 1.0f / l_r0, inv1 = 1.0f / l_r1;
    int r0 = m0 + wm0 + g, r1 = r0 + 8;
    float* c0 = ctx + ((size_t)b * SEQ + r0) * EMB + h * DK;
    float* c1 = ctx + ((size_t)b * SEQ + r1) * EMB + h * DK;
    #pragma unroll
    for (int nt = 0; nt < 8; nt++) {
        int col = nt * 8 + 2 * tig;
        if (r0 < SEQ)
            *reinterpret_cast<float2*>(c0 + col) =
                make_float2(rnd_tf32(acc_o[nt][0] * inv0), rnd_tf32(acc_o[nt][1] * inv0));
        if (r1 < SEQ)
            *reinterpret_cast<float2*>(c1 + col) =
                make_float2(rnd_tf32(acc_o[nt][2] * inv1), rnd_tf32(acc_o[nt][3] * inv1));
    }
}

// ---------------- LayerNorm (tf32-rounded output) -----------------------------
__global__ void __launch_bounds__(256) ln_kernel(
    const float* __restrict__ x, const float* __restrict__ g,
    const float* __restrict__ b, float* __restrict__ out)
{
    int row = blockIdx.x;
    const float* xr = x + (size_t)row * EMB;
    float* orow = out + (size_t)row * EMB;
    int tid = threadIdx.x;

    float v0 = xr[tid], v1 = xr[tid + 256], v2 = xr[tid + 512];
    float s = v0 + v1 + v2;
    __shared__ float red[8];
    #pragma unroll
    for (int o = 16; o; o >>= 1) s += __shfl_xor_sync(0xffffffffu, s, o);
    if ((tid & 31) == 0) red[tid >> 5] = s;
    __syncthreads();
    float tot = 0.f;
    #pragma unroll
    for (int i = 0; i < 8; i++) tot += red[i];
    float mu = tot * (1.0f / EMB);
    __syncthreads();
    float d0 = v0 - mu, d1 = v1 - mu, d2 = v2 - mu;
    float qv = d0 * d0 + d1 * d1 + d2 * d2;
    #pragma unroll
    for (int o = 16; o; o >>= 1) qv += __shfl_xor_sync(0xffffffffu, qv, o);
    if ((tid & 31) == 0) red[tid >> 5] = qv;
    __syncthreads();
    float tot2 = 0.f;
    #pragma unroll
    for (int i = 0; i < 8; i++) tot2 += red[i];
    float rstd = rsqrtf(tot2 * (1.0f / EMB) + 1e-5f);

    orow[tid]       = rnd_tf32(d0 * rstd * g[tid]       + b[tid]);
    orow[tid + 256] = rnd_tf32(d1 * rstd * g[tid + 256] + b[tid + 256]);
    orow[tid + 512] = rnd_tf32(d2 * rstd * g[tid + 512] + b[tid + 512]);
}

// ---------------- weight transpose + tf32 round -------------------------------
__global__ void __launch_bounds__(256) transpose_rnd(
    const float* __restrict__ in, float* __restrict__ out, int K, int N)
{
    __shared__ float t[32][33];
    int bx = blockIdx.x * 32;
    int by = blockIdx.y * 32;
    int tx = threadIdx.x & 31, ty = threadIdx.x >> 5;
    #pragma unroll
    for (int i = 0; i < 32; i += 8)
        t[ty + i][tx] = in[(size_t)(by + ty + i) * N + bx + tx];
    __syncthreads();
    #pragma unroll
    for (int i = 0; i < 32; i += 8)
        out[(size_t)(bx + ty + i) * K + by + tx] = rnd_tf32(t[tx][ty + i]);
}

// ---------------- v head transpose --------------------------------------------
__global__ void __launch_bounds__(256) vtrans_kernel(
    const float* __restrict__ qkv, float* __restrict__ vT)
{
    int z = blockIdx.z, b = z / HEADS, h = z % HEADS;
    int s0 = blockIdx.x * 32, d0 = blockIdx.y * 32;
    __shared__ float t[32][33];
    int tx = threadIdx.x & 31, ty = threadIdx.x >> 5;
    const float* src = qkv + (size_t)b * SEQ * QKVW + 2 * EMB + h * DK;
    #pragma unroll
    for (int i = 0; i < 32; i += 8) {
        int s = s0 + ty + i;
        t[ty + i][tx] = (s < SEQ) ? src[(size_t)s * QKVW + d0 + tx] : 0.f;
    }
    __syncthreads();
    float* dst = vT + ((size_t)z * DK + d0) * SEQP + s0;
    #pragma unroll
    for (int i = 0; i < 32; i += 8) {
        if (s0 + tx < SEQ) dst[(size_t)(ty + i) * SEQP + tx] = t[tx][ty + i];
    }
}

__global__ void concat_bias(const float* __restrict__ bq, const float* __restrict__ bk,
                            const float* __restrict__ bv, float* __restrict__ o)
{
    int i = blockIdx.x * 256 + threadIdx.x;
    if (i < EMB) { o[i] = bq[i]; o[i + EMB] = bk[i]; o[i + 2 * EMB] = bv[i]; }
}

// ---------------- host orchestration ------------------------------------------
extern "C" void kernel_launch(void* const* d_in, const int* in_sizes, int n_in,
                              void* d_out, int out_size)
{
    const float* x     = (const float*)d_in[0];
    const float* wq    = (const float*)d_in[1];
    const float* bq    = (const float*)d_in[2];
    const float* wk    = (const float*)d_in[3];
    const float* bk    = (const float*)d_in[4];
    const float* wv    = (const float*)d_in[5];
    const float* bv    = (const float*)d_in[6];
    const float* wo    = (const float*)d_in[7];
    const float* bo    = (const float*)d_in[8];
    const float* w1    = (const float*)d_in[9];
    const float* bf1   = (const float*)d_in[10];
    const float* w2    = (const float*)d_in[11];
    const float* bf2   = (const float*)d_in[12];
    const float* ln1_g = (const float*)d_in[13];
    const float* ln1_b = (const float*)d_in[14];
    const float* ln2_g = (const float*)d_in[15];
    const float* ln2_b = (const float*)d_in[16];
    float* out = (float*)d_out;

    float *h, *qkv, *vT, *ctx, *x2, *h2, *ff1;
    float *wqkvT, *woT, *w1T, *w2T, *bqkv;
    cudaGetSymbolAddress((void**)&h,     g_h);
    cudaGetSymbolAddress((void**)&qkv,   g_qkv);
    cudaGetSymbolAddress((void**)&vT,    g_vT);
    cudaGetSymbolAddress((void**)&ctx,   g_ctx);
    cudaGetSymbolAddress((void**)&x2,    g_x2);
    cudaGetSymbolAddress((void**)&h2,    g_h2);
    cudaGetSymbolAddress((void**)&ff1,   g_ff1);
    cudaGetSymbolAddress((void**)&wqkvT, g_wqkvT);
    cudaGetSymbolAddress((void**)&woT,   g_woT);
    cudaGetSymbolAddress((void**)&w1T,   g_w1T);
    cudaGetSymbolAddress((void**)&w2T,   g_w2T);
    cudaGetSymbolAddress((void**)&bqkv,  g_bqkv);

    const int SM128 = 3 * (128 + 128) * 36 * 4;          // 110592 (3-stage)
    const int SMFL  = (QB * 68 + 4 * 64 * 68) * 4;       // 87040
    cudaFuncSetAttribute(tcgemm<128, true,  false, false, true >, cudaFuncAttributeMaxDynamicSharedMemorySize, SM128);
    cudaFuncSetAttribute(tcgemm<128, true,  false, true,  false>, cudaFuncAttributeMaxDynamicSharedMemorySize, SM128);
    cudaFuncSetAttribute(tcgemm<128, true,  true,  false, true >, cudaFuncAttributeMaxDynamicSharedMemorySize, SM128);
    cudaFuncSetAttribute(flash_kernel, cudaFuncAttributeMaxDynamicSharedMemorySize, SMFL);

    const int M = NTOK;
    const int MT_ = (M + 127) / 128;       // 73
    const int SQ_ = (SEQ + QB - 1) / QB;   // 10

    // weight prep
    transpose_rnd<<<dim3(EMB / 32, EMB / 32), 256>>>(wq, wqkvT,                 EMB, EMB);
    transpose_rnd<<<dim3(EMB / 32, EMB / 32), 256>>>(wk, wqkvT + EMB * EMB,     EMB, EMB);
    transpose_rnd<<<dim3(EMB / 32, EMB / 32), 256>>>(wv, wqkvT + 2 * EMB * EMB, EMB, EMB);
    transpose_rnd<<<dim3(EMB / 32, EMB / 32), 256>>>(wo, woT, EMB, EMB);
    transpose_rnd<<<dim3(DFF / 32, EMB / 32), 256>>>(w1, w1T, EMB, DFF);
    transpose_rnd<<<dim3(EMB / 32, DFF / 32), 256>>>(w2, w2T, DFF, EMB);
    concat_bias<<<3, 256>>>(bq, bk, bv, bqkv);

    // LN1
    ln_kernel<<<M, 256>>>(x, ln1_g, ln1_b, h);

    // fused QKV
    tcgemm<128, true, false, false, true><<<dim3(QKVW / 128, MT_, 1), 256, SM128>>>(
        h, wqkvT, bqkv, nullptr, qkv, M, QKVW, EMB, EMB, EMB, QKVW);

    // v transpose per head
    vtrans_kernel<<<dim3((SEQ + 31) / 32, DK / 32, NBH), 256>>>(qkv, vT);

    // fused attention (QB=64, 128 threads, 2 CTAs/SM)
    flash_kernel<<<dim3(SQ_, NBH), 128, SMFL>>>(qkv, vT, ctx);

    // WO + bias + residual(x)
    tcgemm<128, true, false, true, false><<<dim3(EMB / 128, MT_, 1), 256, SM128>>>(
        ctx, woT, bo, x, x2, M, EMB, EMB, EMB, EMB, EMB);

    // LN2
    ln_kernel<<<M, 256>>>(x2, ln2_g, ln2_b, h2);

    // W1 + bias + GELU
    tcgemm<128, true, true, false, true><<<dim3(DFF / 128, MT_, 1), 256, SM128>>>(
        h2, w1T, bf1, nullptr, ff1, M, DFF, EMB, EMB, EMB, DFF);

    // W2 + bias + residual(x2) -> out
    tcgemm<128, true, false, true, false><<<dim3(EMB / 128, MT_, 1), 256, SM128>>>(
        ff1, w2T, bf2, x2, out, M, EMB, DFF, DFF, DFF, EMB);
}

// round 17
// speedup vs baseline: 1.0223x; 1.0223x over previous
// Transformer encoder block — Round 11: R9 compute config (flash QB=128,
// tcgemm 3-stage BN=128 ldmatrix) + dual-stream overlap of weight prep.
// B=16, S=577, EMB=768, HEADS=12, DK=64, DFF=3072.

#include <cuda_runtime.h>
#include <cstdint>
#include <math.h>

#define EMB   768
#define HEADS 12
#define DK    64
#define DFF   3072
#define BATCH 16
#define SEQ   577
#define SEQP  600
#define NTOK  (BATCH * SEQ)           // 9232
#define NBH   (BATCH * HEADS)         // 192
#define QKVW  (3 * EMB)               // 2304
#define QB    128
#define KB    64
#define NKB   ((SEQ + KB - 1) / KB)   // 10

// ---------------- scratch (device globals) -----------------------------------
__device__ float g_h   [NTOK * EMB];
__device__ float g_qkv [(size_t)NTOK * QKVW];
__device__ float g_vT  [(size_t)NBH * DK * SEQP];
__device__ float g_ctx [NTOK * EMB];
__device__ float g_x2  [NTOK * EMB];
__device__ float g_h2  [NTOK * EMB];
__device__ float g_ff1 [(size_t)NTOK * DFF];
__device__ float g_wqkvT[QKVW * EMB];
__device__ float g_woT [EMB * EMB];
__device__ float g_w1T [DFF * EMB];
__device__ float g_w2T [EMB * DFF];
__device__ float g_bqkv[QKVW];

// ---------------- PTX helpers -------------------------------------------------
__device__ __forceinline__ uint32_t smem_u32(const void* p) {
    uint32_t a;
    asm("{ .reg .u64 t; cvta.to.shared.u64 t, %1; cvt.u32.u64 %0, t; }"
        : "=r"(a) : "l"(p));
    return a;
}
__device__ __forceinline__ float rnd_tf32(float x) {
    float r;
    asm("cvt.rna.tf32.f32 %0, %1;" : "=f"(r) : "f"(x));
    return r;
}
__device__ __forceinline__ void cp_async16(uint32_t dst, const void* src, int srcBytes) {
    asm volatile("cp.async.cg.shared.global [%0], [%1], 16, %2;"
                 :: "r"(dst), "l"(src), "r"(srcBytes) : "memory");
}
__device__ __forceinline__ void cp_commit() {
    asm volatile("cp.async.commit_group;" ::: "memory");
}
template <int N> __device__ __forceinline__ void cp_wait() {
    asm volatile("cp.async.wait_group %0;" :: "n"(N) : "memory");
}
__device__ __forceinline__ void mma_tf32(float* d, const uint32_t* a, const uint32_t* b) {
    asm volatile(
        "mma.sync.aligned.m16n8k8.row.col.f32.tf32.tf32.f32 "
        "{%0,%1,%2,%3}, {%4,%5,%6,%7}, {%8,%9}, {%0,%1,%2,%3};"
        : "+f"(d[0]), "+f"(d[1]), "+f"(d[2]), "+f"(d[3])
        : "r"(a[0]), "r"(a[1]), "r"(a[2]), "r"(a[3]), "r"(b[0]), "r"(b[1]));
}
// ldmatrix on 32-bit data: each 16B "row" = 4 tf32, distributed 4B/lane.
__device__ __forceinline__ void ldsm_x4(uint32_t* r, uint32_t addr) {
    asm volatile("ldmatrix.sync.aligned.m8n8.x4.shared.b16 {%0,%1,%2,%3}, [%4];"
        : "=r"(r[0]), "=r"(r[1]), "=r"(r[2]), "=r"(r[3]) : "r"(addr));
}
__device__ __forceinline__ void ldsm_x2(uint32_t* r, uint32_t addr) {
    asm volatile("ldmatrix.sync.aligned.m8n8.x2.shared.b16 {%0,%1}, [%2];"
        : "=r"(r[0]), "=r"(r[1]) : "r"(addr));
}

// ---------------- generic tf32 mma.sync GEMM (dense projections) --------------
// BM=128, BN=128, BK=32. 3-stage cp.async pipeline, single __syncthreads per
// chunk, 2 blocks/SM. (R9)
template <int BN, bool BIAS, bool GELU, bool RES, bool RND>
__global__ void __launch_bounds__(256, 2) tcgemm(
    const float* __restrict__ A, const float* __restrict__ B,
    const float* __restrict__ bias, const float* __restrict__ res,
    float* __restrict__ C, int M, int N, int K,
    int lda, int ldb, int ldc)
{
    constexpr int WCOLS = 4;
    constexpr int WM = 64;
    constexpr int WN = BN / WCOLS;         // 32
    constexpr int MT = 4;
    constexpr int NT = WN / 8;             // 4
    constexpr int SA = 36;
    constexpr int ASTGF = 128 * SA;
    constexpr int BSTGF = BN * SA;
    constexpr int STGF  = ASTGF + BSTGF;

    extern __shared__ float smem[];
    const uint32_t sb = smem_u32(smem);
    const int tid = threadIdx.x;
    const int wid = tid >> 5, lane = tid & 31;
    const int g = lane >> 2, tig = lane & 3;
    const int wr = wid / WCOLS, wc = wid % WCOLS;
    const int wm0 = wr * WM, wn0 = wc * WN;

    const int aOff = (lane & 15) * SA + 4 * (lane >> 4);
    const int bOff = (lane & 7) * SA + 4 * ((lane >> 3) & 1);

    const int m0 = blockIdx.y * 128, n0 = blockIdx.x * BN;
    const int nCh = (K + 31) >> 5;

    auto loadA = [&](int c, int buf) {
        uint32_t base = sb + (uint32_t)(buf * STGF) * 4u;
        int k0 = c << 5;
        #pragma unroll
        for (int i = 0; i < 4; i++) {
            int s = tid + i * 256, r = s >> 3, sg = s & 7;
            int gm = m0 + r, kb = k0 + sg * 4;
            int bytes = 0;
            if (gm < M) { int rem = (K - kb) * 4; bytes = rem >= 16 ? 16 : (rem > 0 ? rem : 0); }
            const float* src = A + (size_t)(gm < M ? gm : 0) * lda + (kb < K ? kb : 0);
            cp_async16(base + (uint32_t)(r * SA * 4 + sg * 16), src, bytes);
        }
    };
    auto loadB = [&](int c, int buf) {
        uint32_t base = sb + (uint32_t)(buf * STGF + ASTGF) * 4u;
        int k0 = c << 5;
        #pragma unroll
        for (int i = 0; i < BN / 32; i++) {
            int s = tid + i * 256, r = s >> 3, sg = s & 7;
            int gn = n0 + r, kb = k0 + sg * 4;
            int bytes = 0;
            if (gn < N) { int rem = (K - kb) * 4; bytes = rem >= 16 ? 16 : (rem > 0 ? rem : 0); }
            const float* src = B + (size_t)(gn < N ? gn : 0) * ldb + (kb < K ? kb : 0);
            cp_async16(base + (uint32_t)(r * SA * 4 + sg * 16), src, bytes);
        }
    };

    float acc[MT][NT][4];
    #pragma unroll
    for (int i = 0; i < MT; i++)
        #pragma unroll
        for (int j = 0; j < NT; j++)
            #pragma unroll
            for (int q = 0; q < 4; q++) acc[i][j][q] = 0.f;

    loadA(0, 0); loadB(0, 0); cp_commit();
    if (1 < nCh) { loadA(1, 1); loadB(1, 1); } cp_commit();

    for (int c = 0; c < nCh; c++) {
        const int buf = c % 3;
        cp_wait<1>();
        __syncthreads();
        int p = c + 2;
        if (p < nCh) { loadA(p, p % 3); loadB(p, p % 3); }
        cp_commit();

        const uint32_t AsfB = sb + (uint32_t)(buf * STGF) * 4u;
        const uint32_t BsfB = AsfB + (uint32_t)ASTGF * 4u;
        #pragma unroll
        for (int ks = 0; ks < 4; ks++) {
            const int k = ks * 8;
            uint32_t af[MT][4], bf[NT][2];
            #pragma unroll
            for (int mt = 0; mt < MT; mt++)
                ldsm_x4(af[mt], AsfB + (uint32_t)((wm0 + mt * 16) * SA + aOff + k) * 4u);
            #pragma unroll
            for (int nt = 0; nt < NT; nt++)
                ldsm_x2(bf[nt], BsfB + (uint32_t)((wn0 + nt * 8) * SA + bOff + k) * 4u);
            #pragma unroll
            for (int mt = 0; mt < MT; mt++)
                #pragma unroll
                for (int nt = 0; nt < NT; nt++)
                    mma_tf32(acc[mt][nt], af[mt], bf[nt]);
        }
    }

    #pragma unroll
    for (int mt = 0; mt < MT; mt++) {
        #pragma unroll
        for (int nt = 0; nt < NT; nt++) {
            int gm = m0 + wm0 + mt * 16 + g;
            int gn = n0 + wn0 + nt * 8 + 2 * tig;
            #pragma unroll
            for (int half = 0; half < 2; half++) {
                int gmr = gm + half * 8;
                if (gmr >= M) continue;
                float v0 = acc[mt][nt][half * 2 + 0];
                float v1 = acc[mt][nt][half * 2 + 1];
                if (BIAS) { v0 += bias[gn]; v1 += bias[gn + 1]; }
                if (GELU) {
                    v0 = 0.5f * v0 * (1.0f + erff(v0 * 0.7071067811865475f));
                    v1 = 0.5f * v1 * (1.0f + erff(v1 * 0.7071067811865475f));
                }
                float* crow = C + (size_t)gmr * ldc;
                if (RES) {
                    const float* rrow = res + (size_t)gmr * ldc;
                    v0 += rrow[gn]; v1 += rrow[gn + 1];
                }
                if (RND) { v0 = rnd_tf32(v0); v1 = rnd_tf32(v1); }
                *reinterpret_cast<float2*>(crow + gn) = make_float2(v0, v1);
            }
        }
    }
}

// ---------------- fused flash attention (R9: QB=128, 256 threads) -------------
__global__ void __launch_bounds__(256) flash_kernel(
    const float* __restrict__ qkv, const float* __restrict__ vT,
    float* __restrict__ ctx)
{
    constexpr int ST = 68;
    extern __shared__ float fsm[];
    float* Qs = fsm;
    const uint32_t sb = smem_u32(fsm);
    const uint32_t ks_off = 128 * ST * 4u;
    const uint32_t vs_off = ks_off + 2 * 64 * ST * 4u;

    const int tid = threadIdx.x, wid = tid >> 5, lane = tid & 31;
    const int g = lane >> 2, tig = lane & 3;
    const int wm0 = wid * 16;
    const int z = blockIdx.y, b = z / HEADS, h = z % HEADS;
    const int m0 = blockIdx.x * QB;

    const int aOff = (lane & 15) * ST + 4 * (lane >> 4);
    const int bOff = (lane & 7) * ST + 4 * ((lane >> 3) & 1);

    const float* Qg = qkv + (size_t)b * SEQ * QKVW + h * DK;
    const float* Kg = qkv + (size_t)b * SEQ * QKVW + EMB + h * DK;
    const float* Vg = vT + (size_t)z * DK * SEQP;

    #pragma unroll
    for (int i = 0; i < 8; i++) {
        int s = tid + i * 256, r = s >> 4, sg = s & 15;
        int gm = m0 + r;
        int bytes = (gm < SEQ) ? 16 : 0;
        cp_async16(sb + (uint32_t)(r * ST + sg * 4) * 4u,
                   Qg + (size_t)(gm < SEQ ? gm : 0) * QKVW + sg * 4, bytes);
    }
    cp_commit();

    auto loadKV = [&](int j, int buf) {
        int k0 = j * KB;
        #pragma unroll
        for (int i = 0; i < 4; i++) {
            int s = tid + i * 256, r = s >> 4, sg = s & 15;
            int gs = k0 + r;
            int bytes = (gs < SEQ) ? 16 : 0;
            cp_async16(sb + ks_off + (uint32_t)(buf * 64 * ST + r * ST + sg * 4) * 4u,
                       Kg + (size_t)(gs < SEQ ? gs : 0) * QKVW + sg * 4, bytes);
        }
        #pragma unroll
        for (int i = 0; i < 4; i++) {
            int s = tid + i * 256, r = s >> 4, sg = s & 15;
            int col = k0 + sg * 4;
            int bytes = (col + 4 <= SEQP) ? 16 : 0;
            cp_async16(sb + vs_off + (uint32_t)(buf * 64 * ST + r * ST + sg * 4) * 4u,
                       Vg + (size_t)r * SEQP + (bytes ? col : 0), bytes);
        }
    };
    loadKV(0, 0);
    cp_commit();

    cp_wait<1>();
    __syncthreads();
    uint32_t qf[8][4];
    #pragma unroll
    for (int ks = 0; ks < 8; ks++)
        ldsm_x4(qf[ks], sb + (uint32_t)(wm0 * ST + aOff + ks * 8) * 4u);

    float m_r0 = -1e30f, m_r1 = -1e30f, l_r0 = 0.f, l_r1 = 0.f;
    float acc_o[8][4];
    #pragma unroll
    for (int nt = 0; nt < 8; nt++)
        #pragma unroll
        for (int q = 0; q < 4; q++) acc_o[nt][q] = 0.f;

    for (int j = 0; j < NKB; j++) {
        const int buf = j & 1;
        cp_wait<0>();
        __syncthreads();
        if (j + 1 < NKB) loadKV(j + 1, buf ^ 1);
        cp_commit();

        const uint32_t KbB = sb + ks_off + (uint32_t)(buf * 64 * ST) * 4u;
        const uint32_t VbB = sb + vs_off + (uint32_t)(buf * 64 * ST) * 4u;

        float s_acc[8][4];
        #pragma unroll
        for (int nt = 0; nt < 8; nt++)
            #pragma unroll
            for (int q = 0; q < 4; q++) s_acc[nt][q] = 0.f;
        #pragma unroll
        for (int ks = 0; ks < 8; ks++) {
            const int k = ks * 8;
            uint32_t bf[8][2];
            #pragma unroll
            for (int nt = 0; nt < 8; nt++)
                ldsm_x2(bf[nt], KbB + (uint32_t)(nt * 8 * ST + bOff + k) * 4u);
            #pragma unroll
            for (int nt = 0; nt < 8; nt++)
                mma_tf32(s_acc[nt], qf[ks], bf[nt]);
        }

        const int colbase = j * KB;
        float mx0 = -1e30f, mx1 = -1e30f;
        #pragma unroll
        for (int nt = 0; nt < 8; nt++) {
            int c0 = colbase + nt * 8 + 2 * tig;
            if (c0 >= SEQ)     { s_acc[nt][0] = -1e30f; s_acc[nt][2] = -1e30f; }
            if (c0 + 1 >= SEQ) { s_acc[nt][1] = -1e30f; s_acc[nt][3] = -1e30f; }
            mx0 = fmaxf(mx0, fmaxf(s_acc[nt][0], s_acc[nt][1]));
            mx1 = fmaxf(mx1, fmaxf(s_acc[nt][2], s_acc[nt][3]));
        }
        mx0 = fmaxf(mx0, __shfl_xor_sync(0xffffffffu, mx0, 1));
        mx0 = fmaxf(mx0, __shfl_xor_sync(0xffffffffu, mx0, 2));
        mx1 = fmaxf(mx1, __shfl_xor_sync(0xffffffffu, mx1, 1));
        mx1 = fmaxf(mx1, __shfl_xor_sync(0xffffffffu, mx1, 2));

        float mn0 = fmaxf(m_r0, mx0), mn1 = fmaxf(m_r1, mx1);
        float al0 = __expf(m_r0 - mn0), al1 = __expf(m_r1 - mn1);
        m_r0 = mn0; m_r1 = mn1;

        float sum0 = 0.f, sum1 = 0.f;
        #pragma unroll
        for (int nt = 0; nt < 8; nt++) {
            s_acc[nt][0] = __expf(s_acc[nt][0] - mn0);
            s_acc[nt][1] = __expf(s_acc[nt][1] - mn0);
            s_acc[nt][2] = __expf(s_acc[nt][2] - mn1);
            s_acc[nt][3] = __expf(s_acc[nt][3] - mn1);
            sum0 += s_acc[nt][0] + s_acc[nt][1];
            sum1 += s_acc[nt][2] + s_acc[nt][3];
        }
        sum0 += __shfl_xor_sync(0xffffffffu, sum0, 1);
        sum0 += __shfl_xor_sync(0xffffffffu, sum0, 2);
        sum1 += __shfl_xor_sync(0xffffffffu, sum1, 1);
        sum1 += __shfl_xor_sync(0xffffffffu, sum1, 2);
        l_r0 = l_r0 * al0 + sum0;
        l_r1 = l_r1 * al1 + sum1;

        #pragma unroll
        for (int nt = 0; nt < 8; nt++) {
            acc_o[nt][0] *= al0; acc_o[nt][1] *= al0;
            acc_o[nt][2] *= al1; acc_o[nt][3] *= al1;
        }

        #pragma unroll
        for (int nt = 0; nt < 8; nt++) {
            int col = nt * 8 + 2 * tig;
            *reinterpret_cast<float2*>(Qs + (wm0 + g) * ST + col) =
                make_float2(rnd_tf32(s_acc[nt][0]), rnd_tf32(s_acc[nt][1]));
            *reinterpret_cast<float2*>(Qs + (wm0 + g + 8) * ST + col) =
                make_float2(rnd_tf32(s_acc[nt][2]), rnd_tf32(s_acc[nt][3]));
        }
        __syncwarp();

        #pragma unroll
        for (int ks = 0; ks < 8; ks++) {
            const int k = ks * 8;
            uint32_t af[4], bf[8][2];
            ldsm_x4(af, sb + (uint32_t)(wm0 * ST + aOff + k) * 4u);
            #pragma unroll
            for (int nt = 0; nt < 8; nt++)
                ldsm_x2(bf[nt], VbB + (uint32_t)(nt * 8 * ST + bOff + k) * 4u);
            #pragma unroll
            for (int nt = 0; nt < 8; nt++)
                mma_tf32(acc_o[nt], af, bf[nt]);
        }
        __syncwarp();
    }

    float inv0 = 1.0f / l_r0, inv1 = 1.0f / l_r1;
    int r0 = m0 + wm0 + g, r1 = r0 + 8;
    float* c0 = ctx + ((size_t)b * SEQ + r0) * EMB + h * DK;
    float* c1 = ctx + ((size_t)b * SEQ + r1) * EMB + h * DK;
    #pragma unroll
    for (int nt = 0; nt < 8; nt++) {
        int col = nt * 8 + 2 * tig;
        if (r0 < SEQ)
            *reinterpret_cast<float2*>(c0 + col) =
                make_float2(rnd_tf32(acc_o[nt][0] * inv0), rnd_tf32(acc_o[nt][1] * inv0));
        if (r1 < SEQ)
            *reinterpret_cast<float2*>(c1 + col) =
                make_float2(rnd_tf32(acc_o[nt][2] * inv1), rnd_tf32(acc_o[nt][3] * inv1));
    }
}

// ---------------- LayerNorm (tf32-rounded output) -----------------------------
__global__ void __launch_bounds__(256) ln_kernel(
    const float* __restrict__ x, const float* __restrict__ g,
    const float* __restrict__ b, float* __restrict__ out)
{
    int row = blockIdx.x;
    const float* xr = x + (size_t)row * EMB;
    float* orow = out + (size_t)row * EMB;
    int tid = threadIdx.x;

    float v0 = xr[tid], v1 = xr[tid + 256], v2 = xr[tid + 512];
    float s = v0 + v1 + v2;
    __shared__ float red[8];
    #pragma unroll
    for (int o = 16; o; o >>= 1) s += __shfl_xor_sync(0xffffffffu, s, o);
    if ((tid & 31) == 0) red[tid >> 5] = s;
    __syncthreads();
    float tot = 0.f;
    #pragma unroll
    for (int i = 0; i < 8; i++) tot += red[i];
    float mu = tot * (1.0f / EMB);
    __syncthreads();
    float d0 = v0 - mu, d1 = v1 - mu, d2 = v2 - mu;
    float qv = d0 * d0 + d1 * d1 + d2 * d2;
    #pragma unroll
    for (int o = 16; o; o >>= 1) qv += __shfl_xor_sync(0xffffffffu, qv, o);
    if ((tid & 31) == 0) red[tid >> 5] = qv;
    __syncthreads();
    float tot2 = 0.f;
    #pragma unroll
    for (int i = 0; i < 8; i++) tot2 += red[i];
    float rstd = rsqrtf(tot2 * (1.0f / EMB) + 1e-5f);

    orow[tid]       = rnd_tf32(d0 * rstd * g[tid]       + b[tid]);
    orow[tid + 256] = rnd_tf32(d1 * rstd * g[tid + 256] + b[tid + 256]);
    orow[tid + 512] = rnd_tf32(d2 * rstd * g[tid + 512] + b[tid + 512]);
}

// ---------------- weight transpose + tf32 round -------------------------------
__global__ void __launch_bounds__(256) transpose_rnd(
    const float* __restrict__ in, float* __restrict__ out, int K, int N)
{
    __shared__ float t[32][33];
    int bx = blockIdx.x * 32;
    int by = blockIdx.y * 32;
    int tx = threadIdx.x & 31, ty = threadIdx.x >> 5;
    #pragma unroll
    for (int i = 0; i < 32; i += 8)
        t[ty + i][tx] = in[(size_t)(by + ty + i) * N + bx + tx];
    __syncthreads();
    #pragma unroll
    for (int i = 0; i < 32; i += 8)
        out[(size_t)(bx + ty + i) * K + by + tx] = rnd_tf32(t[tx][ty + i]);
}

// ---------------- v head transpose --------------------------------------------
__global__ void __launch_bounds__(256) vtrans_kernel(
    const float* __restrict__ qkv, float* __restrict__ vT)
{
    int z = blockIdx.z, b = z / HEADS, h = z % HEADS;
    int s0 = blockIdx.x * 32, d0 = blockIdx.y * 32;
    __shared__ float t[32][33];
    int tx = threadIdx.x & 31, ty = threadIdx.x >> 5;
    const float* src = qkv + (size_t)b * SEQ * QKVW + 2 * EMB + h * DK;
    #pragma unroll
    for (int i = 0; i < 32; i += 8) {
        int s = s0 + ty + i;
        t[ty + i][tx] = (s < SEQ) ? src[(size_t)s * QKVW + d0 + tx] : 0.f;
    }
    __syncthreads();
    float* dst = vT + ((size_t)z * DK + d0) * SEQP + s0;
    #pragma unroll
    for (int i = 0; i < 32; i += 8) {
        if (s0 + tx < SEQ) dst[(size_t)(ty + i) * SEQP + tx] = t[tx][ty + i];
    }
}

__global__ void concat_bias(const float* __restrict__ bq, const float* __restrict__ bk,
                            const float* __restrict__ bv, float* __restrict__ o)
{
    int i = blockIdx.x * 256 + threadIdx.x;
    if (i < EMB) { o[i] = bq[i]; o[i + EMB] = bk[i]; o[i + 2 * EMB] = bv[i]; }
}

// ---------------- host orchestration ------------------------------------------
extern "C" void kernel_launch(void* const* d_in, const int* in_sizes, int n_in,
                              void* d_out, int out_size)
{
    const float* x     = (const float*)d_in[0];
    const float* wq    = (const float*)d_in[1];
    const float* bq    = (const float*)d_in[2];
    const float* wk    = (const float*)d_in[3];
    const float* bk    = (const float*)d_in[4];
    const float* wv    = (const float*)d_in[5];
    const float* bv    = (const float*)d_in[6];
    const float* wo    = (const float*)d_in[7];
    const float* bo    = (const float*)d_in[8];
    const float* w1    = (const float*)d_in[9];
    const float* bf1   = (const float*)d_in[10];
    const float* w2    = (const float*)d_in[11];
    const float* bf2   = (const float*)d_in[12];
    const float* ln1_g = (const float*)d_in[13];
    const float* ln1_b = (const float*)d_in[14];
    const float* ln2_g = (const float*)d_in[15];
    const float* ln2_b = (const float*)d_in[16];
    float* out = (float*)d_out;

    float *h, *qkv, *vT, *ctx, *x2, *h2, *ff1;
    float *wqkvT, *woT, *w1T, *w2T, *bqkv;
    cudaGetSymbolAddress((void**)&h,     g_h);
    cudaGetSymbolAddress((void**)&qkv,   g_qkv);
    cudaGetSymbolAddress((void**)&vT,    g_vT);
    cudaGetSymbolAddress((void**)&ctx,   g_ctx);
    cudaGetSymbolAddress((void**)&x2,    g_x2);
    cudaGetSymbolAddress((void**)&h2,    g_h2);
    cudaGetSymbolAddress((void**)&ff1,   g_ff1);
    cudaGetSymbolAddress((void**)&wqkvT, g_wqkvT);
    cudaGetSymbolAddress((void**)&woT,   g_woT);
    cudaGetSymbolAddress((void**)&w1T,   g_w1T);
    cudaGetSymbolAddress((void**)&w2T,   g_w2T);
    cudaGetSymbolAddress((void**)&bqkv,  g_bqkv);

    const int SM128 = 3 * (128 + 128) * 36 * 4;          // 110592 (3-stage)
    const int SMFL  = (128 * 68 + 4 * 64 * 68) * 4;      // 104448
    cudaFuncSetAttribute(tcgemm<128, true,  false, false, true >, cudaFuncAttributeMaxDynamicSharedMemorySize, SM128);
    cudaFuncSetAttribute(tcgemm<128, true,  false, true,  false>, cudaFuncAttributeMaxDynamicSharedMemorySize, SM128);
    cudaFuncSetAttribute(tcgemm<128, true,  true,  false, true >, cudaFuncAttributeMaxDynamicSharedMemorySize, SM128);
    cudaFuncSetAttribute(flash_kernel, cudaFuncAttributeMaxDynamicSharedMemorySize, SMFL);

    // one-time side stream + events (created on the first, non-captured call)
    static cudaStream_t s1 = nullptr;
    static cudaEvent_t evFork = nullptr, evQKVprep = nullptr, evWprep = nullptr;
    if (s1 == nullptr) {
        cudaStreamCreateWithFlags(&s1, cudaStreamNonBlocking);
        cudaEventCreateWithFlags(&evFork,    cudaEventDisableTiming);
        cudaEventCreateWithFlags(&evQKVprep, cudaEventDisableTiming);
        cudaEventCreateWithFlags(&evWprep,   cudaEventDisableTiming);
    }
    cudaStream_t s0 = 0;    // capture/default stream

    const int M = NTOK;
    const int MT_ = (M + 127) / 128;       // 73
    const int ST_ = (SEQ + 127) / 128;     // 5

    // ---- fork: weight prep on s1, LN1 on s0 ----
    cudaEventRecord(evFork, s0);
    cudaStreamWaitEvent(s1, evFork, 0);

    transpose_rnd<<<dim3(EMB / 32, EMB / 32), 256, 0, s1>>>(wq, wqkvT,                 EMB, EMB);
    transpose_rnd<<<dim3(EMB / 32, EMB / 32), 256, 0, s1>>>(wk, wqkvT + EMB * EMB,     EMB, EMB);
    transpose_rnd<<<dim3(EMB / 32, EMB / 32), 256, 0, s1>>>(wv, wqkvT + 2 * EMB * EMB, EMB, EMB);
    concat_bias<<<3, 256, 0, s1>>>(bq, bk, bv, bqkv);
    cudaEventRecord(evQKVprep, s1);
    transpose_rnd<<<dim3(EMB / 32, EMB / 32), 256, 0, s1>>>(wo, woT, EMB, EMB);
    transpose_rnd<<<dim3(DFF / 32, EMB / 32), 256, 0, s1>>>(w1, w1T, EMB, DFF);
    transpose_rnd<<<dim3(EMB / 32, DFF / 32), 256, 0, s1>>>(w2, w2T, DFF, EMB);
    cudaEventRecord(evWprep, s1);

    // LN1 (independent of weight prep)
    ln_kernel<<<M, 256, 0, s0>>>(x, ln1_g, ln1_b, h);

    // ---- join 1: QKV needs wqkvT + bqkv ----
    cudaStreamWaitEvent(s0, evQKVprep, 0);
    tcgemm<128, true, false, false, true><<<dim3(QKVW / 128, MT_, 1), 256, SM128, s0>>>(
        h, wqkvT, bqkv, nullptr, qkv, M, QKVW, EMB, EMB, EMB, QKVW);

    // v transpose per head
    vtrans_kernel<<<dim3((SEQ + 31) / 32, DK / 32, NBH), 256, 0, s0>>>(qkv, vT);

    // fused attention
    flash_kernel<<<dim3(ST_, NBH), 256, SMFL, s0>>>(qkv, vT, ctx);

    // ---- join 2: WO/W1/W2 need woT/w1T/w2T ----
    cudaStreamWaitEvent(s0, evWprep, 0);

    // WO + bias + residual(x)
    tcgemm<128, true, false, true, false><<<dim3(EMB / 128, MT_, 1), 256, SM128, s0>>>(
        ctx, woT, bo, x, x2, M, EMB, EMB, EMB, EMB, EMB);

    // LN2
    ln_kernel<<<M, 256, 0, s0>>>(x2, ln2_g, ln2_b, h2);

    // W1 + bias + GELU
    tcgemm<128, true, true, false, true><<<dim3(DFF / 128, MT_, 1), 256, SM128, s0>>>(
        h2, w1T, bf1, nullptr, ff1, M, DFF, EMB, EMB, EMB, DFF);

    // W2 + bias + residual(x2) -> out
    tcgemm<128, true, false, true, false><<<dim3(EMB / 128, MT_, 1), 256, SM128, s0>>>(
        ff1, w2T, bf2, x2, out, M, EMB, DFF, DFF, DFF, EMB);
}